// round 10
// baseline (speedup 1.0000x reference)
#include <cuda_runtime.h>
#include <cuda_fp16.h>
#include <cstdint>

#define B_ 8
#define N_ 2048
#define F_ 128
#define BK 16

// ---------------- scratch (device globals; no allocs) ----------------
__device__ float g_dinv[B_ * N_];          // 64 KB
__device__ float g_y[B_ * N_ * F_];        // 8 MB fp32 [b][m][f]
__device__ __half g_yt[B_ * F_ * N_];      // 4 MB fp16 [b][f][m]
__device__ __half g_adj16[(size_t)B_ * N_ * N_];  // 67 MB fp16 adj

// ---------------- helpers ----------------
__device__ __forceinline__ uint32_t smem_u32(const void* p) {
    uint32_t a;
    asm("{ .reg .u64 t; cvta.to.shared.u64 t, %1; cvt.u32.u64 %0, t; }" : "=r"(a) : "l"(p));
    return a;
}
__device__ __forceinline__ void cp16(uint32_t dst, const void* src) {
    asm volatile("cp.async.cg.shared.global [%0], [%1], 16;" :: "r"(dst), "l"(src) : "memory");
}
__device__ __forceinline__ unsigned long long pack2(float lo, float hi) {
    unsigned long long r;
    asm("mov.b64 %0, {%1, %2};" : "=l"(r) : "f"(lo), "f"(hi));
    return r;
}
__device__ __forceinline__ void unpack2(unsigned long long v, float& lo, float& hi) {
    asm("mov.b64 {%0, %1}, %2;" : "=f"(lo), "=f"(hi) : "l"(v));
}
__device__ __forceinline__ void fma2(unsigned long long& d, unsigned long long a,
                                     unsigned long long b) {
    asm("fma.rn.f32x2 %0, %1, %2, %0;" : "+l"(d) : "l"(a), "l"(b));
}
__device__ __forceinline__ void mma_f16(float* c, const uint32_t* a, const uint32_t* bb) {
    asm volatile(
        "mma.sync.aligned.m16n8k16.row.col.f32.f16.f16.f32 "
        "{%0,%1,%2,%3}, {%4,%5,%6,%7}, {%8,%9}, {%0,%1,%2,%3};"
        : "+f"(c[0]), "+f"(c[1]), "+f"(c[2]), "+f"(c[3])
        : "r"(a[0]), "r"(a[1]), "r"(a[2]), "r"(a[3]), "r"(bb[0]), "r"(bb[1]));
}
__device__ __forceinline__ void ldm_x4(uint32_t& r0, uint32_t& r1, uint32_t& r2,
                                       uint32_t& r3, uint32_t addr) {
    asm volatile("ldmatrix.sync.aligned.m8n8.x4.shared.b16 {%0,%1,%2,%3}, [%4];"
                 : "=r"(r0), "=r"(r1), "=r"(r2), "=r"(r3) : "r"(addr));
}

// ---------------- K1: row sums -> dinv; adj -> fp16 ----------------
__global__ __launch_bounds__(256) void rowsum_kernel(const float* __restrict__ adj) {
    int row = blockIdx.x;
    const float4* rp = reinterpret_cast<const float4*>(adj + (size_t)row * N_);
    int t = threadIdx.x;
    float4 v0 = rp[t];
    float4 v1 = rp[t + 256];

    // fp16 copy of adj (coalesced 8B stores)
    __half2 a0 = __floats2half2_rn(v0.x, v0.y), a1 = __floats2half2_rn(v0.z, v0.w);
    __half2 a2 = __floats2half2_rn(v1.x, v1.y), a3 = __floats2half2_rn(v1.z, v1.w);
    __half* dst = g_adj16 + (size_t)row * N_;
    *reinterpret_cast<uint2*>(dst + 4 * t) =
        make_uint2(*reinterpret_cast<uint32_t*>(&a0), *reinterpret_cast<uint32_t*>(&a1));
    *reinterpret_cast<uint2*>(dst + 1024 + 4 * t) =
        make_uint2(*reinterpret_cast<uint32_t*>(&a2), *reinterpret_cast<uint32_t*>(&a3));

    float s = (v0.x + v0.y) + (v0.z + v0.w) + (v1.x + v1.y) + (v1.z + v1.w);
#pragma unroll
    for (int off = 16; off > 0; off >>= 1) s += __shfl_xor_sync(0xffffffffu, s, off);
    __shared__ float ws[8];
    if ((t & 31) == 0) ws[t >> 5] = s;
    __syncthreads();
    if (t < 8) {
        float v = ws[t];
#pragma unroll
        for (int off = 4; off > 0; off >>= 1) v += __shfl_xor_sync(0xffu, v, off);
        if (t == 0) g_dinv[row] = rsqrtf(v + 1.0f);
    }
}

// ---------------- K2: y = dinv .* (x @ W^T); also write yT fp16 ----------------
__global__ __launch_bounds__(256) void xw_kernel(const float* __restrict__ x,
                                                 const float* __restrict__ W) {
    __shared__ __align__(16) char sbuf[128 * 136 * 2];
    float (*As)[BK + 1] = reinterpret_cast<float (*)[BK + 1]>(sbuf);
    float (*Bs)[128] = reinterpret_cast<float (*)[128]>(sbuf + 128 * (BK + 1) * 4);
    unsigned short (*Tt)[136] = reinterpret_cast<unsigned short (*)[136]>(sbuf);

    const int rowBase = blockIdx.x * 128;
    const int tid = threadIdx.x;
    const int tx = tid & 15, ty = tid >> 4;
    const int m0 = ty * 8, n0 = tx * 8;

    unsigned long long acc[8][4];
#pragma unroll
    for (int i = 0; i < 8; ++i)
#pragma unroll
        for (int j = 0; j < 4; ++j) acc[i][j] = 0ull;

    for (int kb = 0; kb < F_; kb += BK) {
        {
            int l = tid * 4;
            int r0 = l >> 4, kk = l & 15;
#pragma unroll
            for (int c = 0; c < 2; ++c) {
                int r = r0 + c * 64;
                float4 v = *reinterpret_cast<const float4*>(
                    x + (size_t)(rowBase + r) * F_ + kb + kk);
                As[r][kk + 0] = v.x; As[r][kk + 1] = v.y;
                As[r][kk + 2] = v.z; As[r][kk + 3] = v.w;
            }
        }
        {
#pragma unroll
            for (int c = 0; c < 2; ++c) {
                int q = tid + c * 256;
                int o = q >> 2, kk4 = (q & 3) * 4;
                float4 v = *reinterpret_cast<const float4*>(W + (size_t)o * F_ + kb + kk4);
                Bs[kk4 + 0][o] = v.x; Bs[kk4 + 1][o] = v.y;
                Bs[kk4 + 2][o] = v.z; Bs[kk4 + 3][o] = v.w;
            }
        }
        __syncthreads();
#pragma unroll
        for (int kk = 0; kk < BK; ++kk) {
            float4 b0 = *reinterpret_cast<const float4*>(&Bs[kk][n0]);
            float4 b1 = *reinterpret_cast<const float4*>(&Bs[kk][n0 + 4]);
            unsigned long long bb[4] = {pack2(b0.x, b0.y), pack2(b0.z, b0.w),
                                        pack2(b1.x, b1.y), pack2(b1.z, b1.w)};
#pragma unroll
            for (int i = 0; i < 8; ++i) {
                float a = As[m0 + i][kk];
                unsigned long long aa = pack2(a, a);
#pragma unroll
                for (int j = 0; j < 4; ++j) fma2(acc[i][j], aa, bb[j]);
            }
        }
        __syncthreads();
    }

    float oa[8][8];
#pragma unroll
    for (int i = 0; i < 8; ++i) {
        int r = rowBase + m0 + i;
        float di = g_dinv[r];
        unpack2(acc[i][0], oa[i][0], oa[i][1]);
        unpack2(acc[i][1], oa[i][2], oa[i][3]);
        unpack2(acc[i][2], oa[i][4], oa[i][5]);
        unpack2(acc[i][3], oa[i][6], oa[i][7]);
#pragma unroll
        for (int j = 0; j < 8; ++j) oa[i][j] *= di;
        float* yp = g_y + (size_t)r * F_ + n0;
        *reinterpret_cast<float4*>(yp) = make_float4(oa[i][0], oa[i][1], oa[i][2], oa[i][3]);
        *reinterpret_cast<float4*>(yp + 4) = make_float4(oa[i][4], oa[i][5], oa[i][6], oa[i][7]);
    }

    const int b = rowBase / N_;
    const int mloc0 = rowBase % N_;
#pragma unroll
    for (int i = 0; i < 8; ++i)
#pragma unroll
        for (int j = 0; j < 8; ++j) {
            __half h = __float2half_rn(oa[i][j]);
            Tt[n0 + j][m0 + i] = *reinterpret_cast<unsigned short*>(&h);
        }
    __syncthreads();
    {
        int f = tid >> 1, half = tid & 1;
        const uint4* src = reinterpret_cast<const uint4*>(&Tt[f][half * 64]);
        uint4* dst = reinterpret_cast<uint4*>(
            g_yt + ((size_t)b * F_ + f) * N_ + mloc0 + half * 64);
#pragma unroll
        for (int q = 0; q < 8; ++q) dst[q] = src[q];
    }
}

// ---------------- K3: fp16 mma.sync GEMM, pure cp.async + ldmatrix ----------------
// CTA: 128x128 tile, 8 warps (2x4), warp tile 64x32, KC=128, double-buffered.
// Row stride 272 B -> conflict-free ldmatrix phases.
#define KC 128
#define RPAD 272
#define STG_B_OFF 34816
#define STAGE_SZ 69632
#define K3_SMEM (2 * STAGE_SZ)

__global__ __launch_bounds__(256, 1) void spmm_mma(const float* __restrict__ bias,
                                                   float* __restrict__ out) {
    extern __shared__ __align__(16) char smem[];
    const uint32_t sb = smem_u32(smem);
    const int tid = threadIdx.x;
    const int wid = tid >> 5, lane = tid & 31;
    const int g = lane >> 2, t = lane & 3;
    const int warpM = wid >> 2, warpC = wid & 3;
    const int b = blockIdx.y, rowBase = blockIdx.x * 128;

    const __half* A16 = g_adj16 + ((size_t)b * N_ + rowBase) * N_;
    const __half* Yt = g_yt + (size_t)b * F_ * N_;

    // loader indexing: 16 rows x 16 chunks (16B) per pass, 8 passes per operand
    const int lr_ = tid >> 4, lc_ = tid & 15;

    // ldmatrix lane addressing
    const int llr = lane & 7, lgrp = lane >> 3;
    const uint32_t colOff = (lgrp & 2) ? 16u : 0u;
    uint32_t aBase[4], bBase[2];
#pragma unroll
    for (int mt = 0; mt < 4; ++mt) {
        int row = warpM * 64 + mt * 16 + llr + ((lgrp & 1) ? 8 : 0);
        aBase[mt] = (uint32_t)(row * RPAD) + colOff;
    }
#pragma unroll
    for (int p = 0; p < 2; ++p) {
        int f = warpC * 32 + p * 16 + llr + ((lgrp & 1) ? 8 : 0);
        bBase[p] = (uint32_t)(STG_B_OFF + f * RPAD) + colOff;
    }

    float acc[4][4][4];
#pragma unroll
    for (int i = 0; i < 4; ++i)
#pragma unroll
        for (int j = 0; j < 4; ++j)
#pragma unroll
            for (int q = 0; q < 4; ++q) acc[i][j][q] = 0.f;

    // prologue: chunk 0 -> stage 0
#pragma unroll
    for (int j = 0; j < 8; ++j) {
        int r = lr_ + 16 * j;
        cp16(sb + r * RPAD + lc_ * 16, A16 + (size_t)r * N_ + lc_ * 8);
        cp16(sb + STG_B_OFF + r * RPAD + lc_ * 16, Yt + (size_t)r * N_ + lc_ * 8);
    }
    asm volatile("cp.async.commit_group;" ::: "memory");

    for (int it = 0; it < N_ / KC; ++it) {
        const uint32_t curoff = (uint32_t)(it & 1) * STAGE_SZ;
        if (it < N_ / KC - 1) {
            const int kb = (it + 1) * KC;
            const uint32_t nxt = sb + (uint32_t)((it + 1) & 1) * STAGE_SZ;
#pragma unroll
            for (int j = 0; j < 8; ++j) {
                int r = lr_ + 16 * j;
                cp16(nxt + r * RPAD + lc_ * 16, A16 + (size_t)r * N_ + kb + lc_ * 8);
                cp16(nxt + STG_B_OFF + r * RPAD + lc_ * 16, Yt + (size_t)r * N_ + kb + lc_ * 8);
            }
            asm volatile("cp.async.commit_group;" ::: "memory");
            asm volatile("cp.async.wait_group 1;" ::: "memory");
        } else {
            asm volatile("cp.async.wait_group 0;" ::: "memory");
        }
        __syncthreads();

#pragma unroll
        for (int k16 = 0; k16 < 8; ++k16) {
            const uint32_t ko = sb + curoff + k16 * 32;
            uint32_t afr[4][4];
#pragma unroll
            for (int mt = 0; mt < 4; ++mt)
                ldm_x4(afr[mt][0], afr[mt][1], afr[mt][2], afr[mt][3], ko + aBase[mt]);
            uint32_t bfr[2][4];
#pragma unroll
            for (int p = 0; p < 2; ++p)
                ldm_x4(bfr[p][0], bfr[p][1], bfr[p][2], bfr[p][3], ko + bBase[p]);
#pragma unroll
            for (int mt = 0; mt < 4; ++mt)
#pragma unroll
                for (int p = 0; p < 2; ++p) {
                    uint32_t bb0[2] = {bfr[p][0], bfr[p][2]};
                    uint32_t bb1[2] = {bfr[p][1], bfr[p][3]};
                    mma_f16(acc[mt][2 * p], afr[mt], bb0);
                    mma_f16(acc[mt][2 * p + 1], afr[mt], bb1);
                }
        }
        __syncthreads();
    }

    // ---- epilogue: dinv * (acc + y_self) + bias ----
    const float* Yrow = g_y + ((size_t)b * N_ + rowBase) * F_;
    float* Orow = out + ((size_t)b * N_ + rowBase) * F_;
    const float* dv = g_dinv + b * N_ + rowBase;
#pragma unroll
    for (int mt = 0; mt < 4; ++mt) {
        int rl0 = warpM * 64 + mt * 16 + g;
        int rl1 = rl0 + 8;
        float d0 = dv[rl0], d1 = dv[rl1];
#pragma unroll
        for (int nt = 0; nt < 4; ++nt) {
            int c = warpC * 32 + nt * 8 + 2 * t;
            float2 y0 = *reinterpret_cast<const float2*>(Yrow + (size_t)rl0 * F_ + c);
            float2 y1 = *reinterpret_cast<const float2*>(Yrow + (size_t)rl1 * F_ + c);
            float2 bv = *reinterpret_cast<const float2*>(bias + c);
            float2 o0, o1;
            o0.x = d0 * (acc[mt][nt][0] + y0.x) + bv.x;
            o0.y = d0 * (acc[mt][nt][1] + y0.y) + bv.y;
            o1.x = d1 * (acc[mt][nt][2] + y1.x) + bv.x;
            o1.y = d1 * (acc[mt][nt][3] + y1.y) + bv.y;
            *reinterpret_cast<float2*>(Orow + (size_t)rl0 * F_ + c) = o0;
            *reinterpret_cast<float2*>(Orow + (size_t)rl1 * F_ + c) = o1;
        }
    }
}

extern "C" void kernel_launch(void* const* d_in, const int* in_sizes, int n_in,
                              void* d_out, int out_size) {
    const float* x = (const float*)d_in[0];    // [8,2048,128]
    const float* adj = (const float*)d_in[1];  // [8,2048,2048]
    const float* W = (const float*)d_in[2];    // [128,128]
    const float* bias = (const float*)d_in[3]; // [128]
    float* out = (float*)d_out;                // [8,2048,128]

    cudaFuncSetAttribute(spmm_mma, cudaFuncAttributeMaxDynamicSharedMemorySize, K3_SMEM);

    rowsum_kernel<<<B_ * N_, 256>>>(adj);
    xw_kernel<<<(B_ * N_) / 128, 256>>>(x, W);
    spmm_mma<<<dim3(N_ / 128, B_), 256, K3_SMEM>>>(bias, out);
}